// round 14
// baseline (speedup 1.0000x reference)
#include <cuda_runtime.h>
#include <math.h>

#define NB 64
#define NS 4096
#define CHUNKS 8
#define CHUNK 512
#define NTHREADS 256
#define NWARPS 8
#define EPT 2
#define NBLOCKS (NB * CHUNKS)
#define NELEM (NB * NS)
#define EPSF 1e-6f
#define FULLMASK 0xffffffffu

typedef unsigned long long u64;

// Packed pose: each u64 holds (E_value, G_value) as f32x2 (lo = E, hi = G).
struct PP { u64 qw, qx, qy, qz, tx, ty, tz; };
struct Quat { float w, x, y, z; };

#define NEG1_F2 0xBF800000BF800000ULL
#define ONE_F2  0x3F8000003F800000ULL

__device__ u64    g_agg[NBLOCKS][8];
__device__ u64    g_pre[NBLOCKS][8];
__device__ int    g_flag[NBLOCKS];      // gen-coded: 2*gen = agg ready, 2*gen+1 = prefix ready
__device__ double g_accum[6];           // sq_pos, ab_pos, odom_ang, sq_traj, ab_traj, traj_ang
__device__ int    g_gen = 1;
__device__ int    g_done = 0;

// ---- f32x2 packed primitives (sm_100a Blackwell) ----
__device__ __forceinline__ u64 f2mul(u64 a, u64 b) {
    u64 r; asm("mul.rn.f32x2 %0,%1,%2;" : "=l"(r) : "l"(a), "l"(b)); return r;
}
__device__ __forceinline__ u64 f2add(u64 a, u64 b) {
    u64 r; asm("add.rn.f32x2 %0,%1,%2;" : "=l"(r) : "l"(a), "l"(b)); return r;
}
__device__ __forceinline__ u64 f2fma(u64 a, u64 b, u64 c) {
    u64 r; asm("fma.rn.f32x2 %0,%1,%2,%3;" : "=l"(r) : "l"(a), "l"(b), "l"(c)); return r;
}
__device__ __forceinline__ u64 f2sub(u64 a, u64 b) {   // a - b = fma(b, -1, a), exact
    return f2fma(b, NEG1_F2, a);
}
__device__ __forceinline__ u64 f2pack(float lo, float hi) {
    u64 r; asm("mov.b64 %0,{%1,%2};" : "=l"(r) : "f"(lo), "f"(hi)); return r;
}
__device__ __forceinline__ void f2unpack(u64 v, float& lo, float& hi) {
    asm("mov.b64 {%0,%1},%2;" : "=f"(lo), "=f"(hi) : "l"(v));
}

__device__ __forceinline__ PP ppidentity() {
    PP p; p.qw = ONE_F2; p.qx = 0; p.qy = 0; p.qz = 0; p.tx = 0; p.ty = 0; p.tz = 0;
    return p;
}

// Packed compose, both streams at once. C = A then B (q = qa*qb, t = ta + rot(qa, tb)).
__device__ __forceinline__ PP ppcompose(const PP& A, const PP& B) {
    PP C;
    u64 t;
    t = f2mul(A.qz, B.qz); t = f2fma(A.qy, B.qy, t); t = f2fma(A.qx, B.qx, t);
    C.qw = f2sub(f2mul(A.qw, B.qw), t);
    t = f2mul(A.qx, B.qw); t = f2fma(A.qw, B.qx, t); t = f2fma(A.qy, B.qz, t);
    C.qx = f2sub(t, f2mul(A.qz, B.qy));
    t = f2mul(A.qy, B.qw); t = f2fma(A.qw, B.qy, t); t = f2fma(A.qz, B.qx, t);
    C.qy = f2sub(t, f2mul(A.qx, B.qz));
    t = f2mul(A.qz, B.qw); t = f2fma(A.qw, B.qz, t); t = f2fma(A.qx, B.qy, t);
    C.qz = f2sub(t, f2mul(A.qy, B.qx));
    u64 t2x = f2sub(f2mul(A.qy, B.tz), f2mul(A.qz, B.ty)); t2x = f2add(t2x, t2x);
    u64 t2y = f2sub(f2mul(A.qz, B.tx), f2mul(A.qx, B.tz)); t2y = f2add(t2y, t2y);
    u64 t2z = f2sub(f2mul(A.qx, B.ty), f2mul(A.qy, B.tx)); t2z = f2add(t2z, t2z);
    u64 u;
    u = f2add(A.tx, B.tx); u = f2fma(A.qw, t2x, u); u = f2fma(A.qy, t2z, u);
    C.tx = f2sub(u, f2mul(A.qz, t2y));
    u = f2add(A.ty, B.ty); u = f2fma(A.qw, t2y, u); u = f2fma(A.qz, t2x, u);
    C.ty = f2sub(u, f2mul(A.qx, t2z));
    u = f2add(A.tz, B.tz); u = f2fma(A.qw, t2z, u); u = f2fma(A.qx, t2y, u);
    C.tz = f2sub(u, f2mul(A.qy, t2x));
    return C;
}

// Translation-only compose: out = p.t + rot(p.q, x.t), packed.
__device__ __forceinline__ void pprot_add(const PP& p, const PP& x, u64& ox, u64& oy, u64& oz) {
    u64 t2x = f2sub(f2mul(p.qy, x.tz), f2mul(p.qz, x.ty)); t2x = f2add(t2x, t2x);
    u64 t2y = f2sub(f2mul(p.qz, x.tx), f2mul(p.qx, x.tz)); t2y = f2add(t2y, t2y);
    u64 t2z = f2sub(f2mul(p.qx, x.ty), f2mul(p.qy, x.tx)); t2z = f2add(t2z, t2z);
    u64 u;
    u = f2add(p.tx, x.tx); u = f2fma(p.qw, t2x, u); u = f2fma(p.qy, t2z, u);
    ox = f2sub(u, f2mul(p.qz, t2y));
    u = f2add(p.ty, x.ty); u = f2fma(p.qw, t2y, u); u = f2fma(p.qz, t2x, u);
    oy = f2sub(u, f2mul(p.qx, t2z));
    u = f2add(p.tz, x.tz); u = f2fma(p.qw, t2z, u); u = f2fma(p.qx, t2y, u);
    oz = f2sub(u, f2mul(p.qy, t2x));
}

// Normalize both quaternions of a packed pose (publish points only).
__device__ __forceinline__ void ppnorm(PP& p) {
    u64 n = f2mul(p.qw, p.qw);
    n = f2fma(p.qx, p.qx, n); n = f2fma(p.qy, p.qy, n); n = f2fma(p.qz, p.qz, n);
    float nE, nG; f2unpack(n, nE, nG);
    u64 s = f2pack(rsqrtf(nE), rsqrtf(nG));
    p.qw = f2mul(p.qw, s); p.qx = f2mul(p.qx, s);
    p.qy = f2mul(p.qy, s); p.qz = f2mul(p.qz, s);
}

__device__ __forceinline__ PP ppshfl_up(const PP& p, int off) {
    PP r;
    r.qw = __shfl_up_sync(FULLMASK, p.qw, off);
    r.qx = __shfl_up_sync(FULLMASK, p.qx, off);
    r.qy = __shfl_up_sync(FULLMASK, p.qy, off);
    r.qz = __shfl_up_sync(FULLMASK, p.qz, off);
    r.tx = __shfl_up_sync(FULLMASK, p.tx, off);
    r.ty = __shfl_up_sync(FULLMASK, p.ty, off);
    r.tz = __shfl_up_sync(FULLMASK, p.tz, off);
    return r;
}

__device__ __forceinline__ void ppstore(u64* p, const PP& x) {
    p[0]=x.qw; p[1]=x.qx; p[2]=x.qy; p[3]=x.qz; p[4]=x.tx; p[5]=x.ty; p[6]=x.tz;
}
__device__ __forceinline__ PP ppload(const u64* p) {
    PP x;
    x.qw=p[0]; x.qx=p[1]; x.qy=p[2]; x.qz=p[3]; x.tx=p[4]; x.ty=p[5]; x.tz=p[6];
    return x;
}
__device__ __forceinline__ void ppstore_g(u64* p, const PP& x) {
    *(ulonglong2*)(p)     = make_ulonglong2(x.qw, x.qx);
    *(ulonglong2*)(p + 2) = make_ulonglong2(x.qy, x.qz);
    *(ulonglong2*)(p + 4) = make_ulonglong2(x.tx, x.ty);
    p[6] = x.tz;
}
__device__ __forceinline__ PP ppload_g(const u64* p) {
    ulonglong2 a = *(const ulonglong2*)(p), b = *(const ulonglong2*)(p + 2);
    ulonglong2 c = *(const ulonglong2*)(p + 4);
    PP x;
    x.qw=a.x; x.qx=a.y; x.qy=b.x; x.qz=b.y; x.tx=c.x; x.ty=c.y; x.tz=p[6];
    return x;
}

// acos via A&S 4.4.45: |err| <= 2e-8 on [0,1]; input pre-clamped to |x| <= 1-1e-6.
__device__ __forceinline__ float acos_fast(float x) {
    float ax = fabsf(x);
    float p = fmaf(ax, -0.0012624911f, 0.0066700901f);
    p = fmaf(ax, p, -0.0170881256f);
    p = fmaf(ax, p,  0.0308918810f);
    p = fmaf(ax, p, -0.0501743046f);
    p = fmaf(ax, p,  0.0889789874f);
    p = fmaf(ax, p, -0.2145988016f);
    p = fmaf(ax, p,  1.5707963050f);
    float y = 1.0f - ax;
    float v = (y * rsqrtf(y)) * p;       // sqrt(1-ax) * poly
    return (x >= 0.f) ? v : 3.14159265f - v;
}
__device__ __forceinline__ float clamp_c(float c) {
    return fminf(fmaxf(c, -1.f + EPSF), 1.f - EPSF);
}

// Unpack both quats of a packed pose into scalar quats.
__device__ __forceinline__ void pp_unpack_q(const PP& p, Quat& e, Quat& g) {
    f2unpack(p.qw, e.w, g.w); f2unpack(p.qx, e.x, g.x);
    f2unpack(p.qy, e.y, g.y); f2unpack(p.qz, e.z, g.z);
}
__device__ __forceinline__ float qn2(const Quat& q) {
    return q.w*q.w + q.x*q.x + q.y*q.y + q.z*q.z;
}
// conj(g) * e (Hamilton)
__device__ __forceinline__ Quat qconj_mul(const Quat& g, const Quat& e) {
    Quat r;
    r.w = g.w*e.w + g.x*e.x + g.y*e.y + g.z*e.z;
    r.x = g.w*e.x - g.x*e.w - g.y*e.z + g.z*e.y;
    r.y = g.w*e.y + g.x*e.z - g.y*e.w - g.z*e.x;
    r.z = g.w*e.z - g.x*e.y + g.y*e.x - g.z*e.w;
    return r;
}
// dot(r * a, b)
__device__ __forceinline__ float qmul_dot(const Quat& r, const Quat& a, const Quat& b) {
    float mw = r.w*a.w - r.x*a.x - r.y*a.y - r.z*a.z;
    float mx = r.w*a.x + r.x*a.w + r.y*a.z - r.z*a.y;
    float my = r.w*a.y - r.x*a.z + r.y*a.w + r.z*a.x;
    float mz = r.w*a.z + r.x*a.y - r.y*a.x + r.z*a.w;
    return mw*b.w + mx*b.x + my*b.y + mz*b.z;
}

// One trajectory-loss element on packed data.
__device__ __forceinline__ void traj_term(
    const PP& pre, const Quat& r, float K, const PP& x, float acc[6]) {
    u64 ptx, pty, ptz;
    pprot_add(pre, x, ptx, pty, ptz);
    float e0,g0,e1,g1,e2,g2;
    f2unpack(ptx, e0, g0); f2unpack(pty, e1, g1); f2unpack(ptz, e2, g2);
    float d0 = e0-g0, d1 = e1-g1, d2 = e2-g2;
    acc[3] = fmaf(d0, d0, fmaf(d1, d1, fmaf(d2, d2, acc[3])));
    acc[4] += fabsf(d0) + fabsf(d1) + fabsf(d2);
    // angle: cos = 2*dot(r*xE, xG)^2 / (K * |xE|^2 |xG|^2) - 1
    Quat xe, xg;
    pp_unpack_q(x, xe, xg);
    float dq = qmul_dot(r, xe, xg);
    float nn = K * qn2(xe) * qn2(xg);
    float c = clamp_c(fmaf(2.f * dq, __fdividef(dq, nn), -1.f));
    acc[5] += acos_fast(c);
}

__device__ __forceinline__ void block_reduce6_atomic(float v[6]) {
#pragma unroll
    for (int o = 16; o > 0; o >>= 1)
#pragma unroll
        for (int j = 0; j < 6; j++) v[j] += __shfl_down_sync(FULLMASK, v[j], o);
    __shared__ float w[6][NWARPS];
    int lane = threadIdx.x & 31, wid = threadIdx.x >> 5;
    if (lane == 0)
#pragma unroll
        for (int j = 0; j < 6; j++) w[j][wid] = v[j];
    __syncthreads();
    if (threadIdx.x < 6) {
        double s = 0.0;
#pragma unroll
        for (int i = 0; i < NWARPS; i++) s += (double)w[threadIdx.x][i];
        atomicAdd(&g_accum[threadIdx.x], s);
    }
}

// Single fused kernel: EPT=2, 4096 warps in one wave, f32x2-packed dual-stream math.
__global__ void __launch_bounds__(NTHREADS, 4) k_main(
    const float* __restrict__ yhat, const float* __restrict__ gpos,
    const float* __restrict__ gori, float* __restrict__ out) {
    __shared__ u64 sP[NTHREADS][9];      // elem-0 packed pose (7 u64; stride 9 -> 2-way max)
    __shared__ u64 sw[NWARPS][8];        // warp-inclusive packed partials
    __shared__ u64 sexc[8];              // chunk-exclusive packed base
    int tid = threadIdx.x, lane = tid & 31, wid = tid >> 5;
    int bid = blockIdx.x;
    int batch = bid >> 3, chunk = bid & (CHUNKS - 1);
    int s0 = chunk * CHUNK + tid * EPT;
    int idx0 = batch * NS + s0;

    // ---- inputs ----
    const float4* y4 = (const float4*)(yhat + (size_t)idx0 * 6);
    float4 y0 = y4[0], y1 = y4[1], y2 = y4[2];
    const float2* o2 = (const float2*)(gori + (size_t)idx0 * 3);
    float2 q0 = o2[0], q1 = o2[1], q2 = o2[2];
    const float2* p2 = (const float2*)(gpos + (size_t)idx0 * 3);
    float2 p0 = p2[0], p1 = p2[1], pz = p2[2];

    float ea[2][3] = {{y0.x,y0.y,y0.z},{y1.z,y1.w,y2.x}};
    float et[2][3] = {{y0.w,y1.x,y1.y},{y2.y,y2.z,y2.w}};
    float ga[2][3] = {{q0.x,q0.y,q1.x},{q1.y,q2.x,q2.y}};
    float gt[2][3] = {{p0.x,p0.y,p1.x},{p1.y,pz.x,pz.y}};

    // ---- build 2 packed poses, odom terms ----
    float acc[6] = {0.f, 0.f, 0.f, 0.f, 0.f, 0.f};
    PP I;
#pragma unroll
    for (int i = 0; i < EPT; i++) {
        float saE, caE, sbE, cbE, scE, ccE, saG, caG, sbG, cbG, scG, ccG;
        __sincosf(0.5f * ea[i][0], &saE, &caE);
        __sincosf(0.5f * ea[i][1], &sbE, &cbE);
        __sincosf(0.5f * ea[i][2], &scE, &ccE);
        __sincosf(0.5f * ga[i][0], &saG, &caG);
        __sincosf(0.5f * ga[i][1], &sbG, &cbG);
        __sincosf(0.5f * ga[i][2], &scG, &ccG);
        u64 Psa = f2pack(saE, saG), Pca = f2pack(caE, caG);
        u64 Psb = f2pack(sbE, sbG), Pcb = f2pack(cbE, cbG);
        u64 Psc = f2pack(scE, scG), Pcc = f2pack(ccE, ccG);
        u64 t1 = f2mul(Pcc, Pcb), t2 = f2mul(Psc, Psb);
        u64 t3 = f2mul(Pcc, Psb), t4 = f2mul(Psc, Pcb);
        PP X;
        X.qw = f2fma(t1, Pca, f2mul(t2, Psa));               // cc*cb*ca + sc*sb*sa
        X.qx = f2sub(f2mul(t1, Psa), f2mul(t2, Pca));        // cc*cb*sa - sc*sb*ca
        X.qy = f2fma(t3, Pca, f2mul(t4, Psa));               // cc*sb*ca + sc*cb*sa
        X.qz = f2sub(f2mul(t4, Pca), f2mul(t3, Psa));        // sc*cb*ca - cc*sb*sa
        X.tx = f2pack(et[i][0], gt[i][0]);
        X.ty = f2pack(et[i][1], gt[i][1]);
        X.tz = f2pack(et[i][2], gt[i][2]);

        // odom pointwise terms (E vs G = lo vs hi)
        float e0,g0,e1,g1,e2,g2;
        f2unpack(X.tx, e0, g0); f2unpack(X.ty, e1, g1); f2unpack(X.tz, e2, g2);
        float d0 = e0-g0, d1 = e1-g1, d2 = e2-g2;
        acc[0] = fmaf(d0, d0, fmaf(d1, d1, fmaf(d2, d2, acc[0])));
        acc[1] += fabsf(d0) + fabsf(d1) + fabsf(d2);
        Quat xe, xg;
        pp_unpack_q(X, xe, xg);
        float dq = xe.w*xg.w + xe.x*xg.x + xe.y*xg.y + xe.z*xg.z;  // raw quats unit
        acc[2] += acos_fast(clamp_c(fmaf(2.f * dq, dq, -1.f)));

        if (s0 == 0 && i == 0) X = ppidentity();   // shifted[...,0] = I
        if (i == 0) {
            ppstore(sP[tid], X);
            I = X;
        } else {
            I = ppcompose(I, X);
        }
    }

    // ---- warp-level inclusive scan (packed: one compose covers both streams) ----
#pragma unroll
    for (int off = 1; off < 32; off <<= 1) {
        PP le = ppshfl_up(I, off);
        if (lane >= off) I = ppcompose(le, I);
    }
    if (lane == 31) ppstore(sw[wid], I);
    __syncthreads();

    // ---- cross-warp scan (warp 0, 8 entries -> 3 steps) ----
    if (wid == 0) {
        PP te = (lane < NWARPS) ? ppload(sw[lane]) : ppidentity();
#pragma unroll
        for (int off = 1; off < NWARPS; off <<= 1) {
            PP le = ppshfl_up(te, off);
            if (lane >= off && lane < NWARPS) te = ppcompose(le, te);
        }
        if (lane < NWARPS) ppstore(sw[lane], te);
    }
    __syncthreads();

    // ---- thread 0: publish aggregate, lookback (depth <= 7), publish prefix ----
    if (tid == 0) {
        int gen = *(volatile int*)&g_gen;
        int fagg = 2 * gen, fpre = 2 * gen + 1;
        PP a = ppload(sw[NWARPS - 1]);
        ppnorm(a);   // cap norm drift at chunk length
        if (chunk < CHUNKS - 1) {
            ppstore_g(g_agg[bid], a);
            __threadfence();
            atomicExch(&g_flag[bid], fagg);
        }
        PP exc = ppidentity();
        if (chunk > 0) {
            PP accP = ppidentity();
            bool have = false;
            int base = batch * CHUNKS;
            for (int i = bid - 1; i >= base; --i) {
                int f;
                volatile int* vf = g_flag;
                while ((f = vf[i]) < fagg) { __nanosleep(20); }
                __threadfence();
                if (f == fpre) {
                    exc = ppcompose(ppload_g(g_pre[i]), accP);
                    have = true;
                    break;
                } else {
                    accP = ppcompose(ppload_g(g_agg[i]), accP);
                }
            }
            if (!have) exc = accP;
            ppnorm(exc);
        }
        if (chunk < CHUNKS - 1) {
            PP pr = ppcompose(exc, a);
            ppnorm(pr);
            ppstore_g(g_pre[bid], pr);
            __threadfence();
            atomicExch(&g_flag[bid], fpre);
        }
        ppstore(sexc, exc);
    }
    __syncthreads();

    // ---- apply prefixes, trajectory losses (2 elems) ----
    PP base = ppload(sexc);
    if (wid > 0) base = ppcompose(base, ppload(sw[wid - 1]));
    PP LE = ppshfl_up(I, 1);
    PP pre = (lane == 0) ? base : ppcompose(base, LE);

    // elem 0: base = thread-exclusive prefix, x = raw elem-0 packed pose (smem)
    {
        Quat pe, pg;
        pp_unpack_q(pre, pe, pg);
        Quat r0 = qconj_mul(pg, pe);
        float K0 = qn2(pe) * qn2(pg);
        traj_term(pre, r0, K0, ppload(sP[tid]), acc);
    }
    // elem 1: cumulative = warp-base ∘ warp-inclusive
    {
        Quat be, bg;
        pp_unpack_q(base, be, bg);
        Quat rB = qconj_mul(bg, be);
        float KB = qn2(be) * qn2(bg);
        traj_term(base, rB, KB, I, acc);
    }

    block_reduce6_atomic(acc);
    __syncthreads();

    // ---- last block finalizes ----
    if (tid == 0) {
        __threadfence();
        int old = atomicAdd(&g_done, 1);
        if (old == NBLOCKS - 1) {
            __threadfence();
            const double n3 = (double)NELEM * 3.0, n1 = (double)NELEM;
            double odom = g_accum[2] / n1 + (g_accum[0] / n3 + g_accum[1] / n3);
            double traj = g_accum[5] / n1 + (g_accum[3] / n3 + g_accum[4] / n3);
            out[0] = (float)(0.5 * odom + 0.5 * traj);
#pragma unroll
            for (int j = 0; j < 6; j++) g_accum[j] = 0.0;
            g_done = 0;
            __threadfence();
            g_gen = *(volatile int*)&g_gen + 1;
        }
    }
}

extern "C" void kernel_launch(void* const* d_in, const int* in_sizes, int n_in,
                              void* d_out, int out_size) {
    const float* yhat = (const float*)d_in[0];
    const float* gpos = (const float*)d_in[1];
    const float* gori = (const float*)d_in[2];
    k_main<<<NBLOCKS, NTHREADS>>>(yhat, gpos, gori, (float*)d_out);
}

// round 15
// speedup vs baseline: 1.0714x; 1.0714x over previous
#include <cuda_runtime.h>
#include <math.h>

#define NB 64
#define NS 4096
#define CHUNKS 8
#define CHUNK 512
#define NTHREADS 128
#define NWARPS 4
#define EPT 4
#define NBLOCKS (NB * CHUNKS)
#define NELEM (NB * NS)
#define EPSF 1e-6f
#define FULLMASK 0xffffffffu
#define SS_STRIDE 43   // 42 floats used; stride 43 coprime with 32 -> conflict-free

struct Pose { float qw, qx, qy, qz, tx, ty, tz; };
struct Quat { float w, x, y, z; };

__device__ float  g_agg[NBLOCKS][16];
__device__ float  g_pre[NBLOCKS][16];
__device__ int    g_flag[NBLOCKS];        // gen-coded: 2*gen = agg ready, 2*gen+1 = prefix ready
__device__ float  g_partial[6][NBLOCKS];  // per-block partial sums (contention-free)
__device__ int    g_gen = 1;
__device__ int    g_done = 0;

__device__ __forceinline__ Pose pidentity() { return Pose{1.f, 0.f, 0.f, 0.f, 0.f, 0.f, 0.f}; }

// C = A then B: q = qa*qb, t = ta + rot(qa, tb)
__device__ __forceinline__ Pose pcompose(const Pose& A, const Pose& B) {
    Pose C;
    C.qw = A.qw*B.qw - A.qx*B.qx - A.qy*B.qy - A.qz*B.qz;
    C.qx = A.qw*B.qx + A.qx*B.qw + A.qy*B.qz - A.qz*B.qy;
    C.qy = A.qw*B.qy - A.qx*B.qz + A.qy*B.qw + A.qz*B.qx;
    C.qz = A.qw*B.qz + A.qx*B.qy - A.qy*B.qx + A.qz*B.qw;
    float t2x = 2.f * (A.qy*B.tz - A.qz*B.ty);
    float t2y = 2.f * (A.qz*B.tx - A.qx*B.tz);
    float t2z = 2.f * (A.qx*B.ty - A.qy*B.tx);
    C.tx = A.tx + B.tx + A.qw*t2x + (A.qy*t2z - A.qz*t2y);
    C.ty = A.ty + B.ty + A.qw*t2y + (A.qz*t2x - A.qx*t2z);
    C.tz = A.tz + B.tz + A.qw*t2z + (A.qx*t2y - A.qy*t2x);
    return C;
}

__device__ __forceinline__ void pnormq(Pose& p) {
    float s = rsqrtf(p.qw*p.qw + p.qx*p.qx + p.qy*p.qy + p.qz*p.qz);
    p.qw *= s; p.qx *= s; p.qy *= s; p.qz *= s;
}

__device__ __forceinline__ Pose pshfl_up(const Pose& p, int off) {
    Pose r;
    r.qw = __shfl_up_sync(FULLMASK, p.qw, off);
    r.qx = __shfl_up_sync(FULLMASK, p.qx, off);
    r.qy = __shfl_up_sync(FULLMASK, p.qy, off);
    r.qz = __shfl_up_sync(FULLMASK, p.qz, off);
    r.tx = __shfl_up_sync(FULLMASK, p.tx, off);
    r.ty = __shfl_up_sync(FULLMASK, p.ty, off);
    r.tz = __shfl_up_sync(FULLMASK, p.tz, off);
    return r;
}

// Quaternion for R = Rz(c) @ Ry(b) @ Rx(a)
__device__ __forceinline__ void euler_to_quat(float a, float b, float c, Pose& P) {
    float sa, ca, sb, cb, sc, cc;
    __sincosf(0.5f * a, &sa, &ca);
    __sincosf(0.5f * b, &sb, &cb);
    __sincosf(0.5f * c, &sc, &cc);
    P.qw = cc*cb*ca + sc*sb*sa;
    P.qx = cc*cb*sa - sc*sb*ca;
    P.qy = cc*sb*ca + sc*cb*sa;
    P.qz = sc*cb*ca - cc*sb*sa;
}

// acos via A&S 4.4.45: |err| <= 2e-8 on [0,1]; input pre-clamped to |x| <= 1-1e-6.
__device__ __forceinline__ float acos_fast(float x) {
    float ax = fabsf(x);
    float p = fmaf(ax, -0.0012624911f, 0.0066700901f);
    p = fmaf(ax, p, -0.0170881256f);
    p = fmaf(ax, p,  0.0308918810f);
    p = fmaf(ax, p, -0.0501743046f);
    p = fmaf(ax, p,  0.0889789874f);
    p = fmaf(ax, p, -0.2145988016f);
    p = fmaf(ax, p,  1.5707963050f);
    float y = 1.0f - ax;
    float v = (y * rsqrtf(y)) * p;       // sqrt(1-ax) * poly
    return (x >= 0.f) ? v : 3.14159265f - v;
}

__device__ __forceinline__ float clamp_c(float c) {
    return fminf(fmaxf(c, -1.f + EPSF), 1.f - EPSF);
}

__device__ __forceinline__ float qn2p(const Pose& p) {
    return p.qw*p.qw + p.qx*p.qx + p.qy*p.qy + p.qz*p.qz;
}

// conj(g) * e  (Hamilton)
__device__ __forceinline__ Quat qconj_mul(const Pose& g, const Pose& e) {
    Quat r;
    r.w = g.qw*e.qw + g.qx*e.qx + g.qy*e.qy + g.qz*e.qz;
    r.x = g.qw*e.qx - g.qx*e.qw - g.qy*e.qz + g.qz*e.qy;
    r.y = g.qw*e.qy + g.qx*e.qz - g.qy*e.qw - g.qz*e.qx;
    r.z = g.qw*e.qz - g.qx*e.qy + g.qy*e.qx - g.qz*e.qw;
    return r;
}

// dot(r * a.q, b.q)
__device__ __forceinline__ float qmul_dot(const Quat& r, const Pose& a, const Pose& b) {
    float mw = r.w*a.qw - r.x*a.qx - r.y*a.qy - r.z*a.qz;
    float mx = r.w*a.qx + r.x*a.qw + r.y*a.qz - r.z*a.qy;
    float my = r.w*a.qy - r.x*a.qz + r.y*a.qw + r.z*a.qx;
    float mz = r.w*a.qz + r.x*a.qy - r.y*a.qx + r.z*a.qw;
    return mw*b.qw + mx*b.qx + my*b.qy + mz*b.qz;
}

// out = p.t + rot(p.q, x.t)  (translation part of pcompose only)
__device__ __forceinline__ void rot_add(const Pose& p, const Pose& x, float out[3]) {
    float t2x = 2.f * (p.qy*x.tz - p.qz*x.ty);
    float t2y = 2.f * (p.qz*x.tx - p.qx*x.tz);
    float t2z = 2.f * (p.qx*x.ty - p.qy*x.tx);
    out[0] = p.tx + x.tx + p.qw*t2x + (p.qy*t2z - p.qz*t2y);
    out[1] = p.ty + x.ty + p.qw*t2y + (p.qz*t2x - p.qx*t2z);
    out[2] = p.tz + x.tz + p.qw*t2z + (p.qx*t2y - p.qy*t2x);
}

// One trajectory-loss element: translations via rot_add, angle via relative-quat r.
__device__ __forceinline__ void traj_term(
    const Pose& preE, const Pose& preG, const Quat& r, float K,
    const Pose& xE, const Pose& xG, float acc[6]) {
    float tE[3], tG[3];
    rot_add(preE, xE, tE);
    rot_add(preG, xG, tG);
#pragma unroll
    for (int k = 0; k < 3; k++) {
        float d = tE[k] - tG[k];
        acc[3] = fmaf(d, d, acc[3]);
        acc[4] += fabsf(d);
    }
    float dq = qmul_dot(r, xE, xG);
    float nn = K * qn2p(xE) * qn2p(xG);
    float c = clamp_c(fmaf(2.f * dq, __fdividef(dq, nn), -1.f));
    acc[5] += acos_fast(c);
}

__device__ __forceinline__ void pstore_s(float* p, const Pose& x) {
    p[0]=x.qw; p[1]=x.qx; p[2]=x.qy; p[3]=x.qz; p[4]=x.tx; p[5]=x.ty; p[6]=x.tz;
}
__device__ __forceinline__ Pose pload_s(const float* p) {
    Pose x;
    x.qw=p[0]; x.qx=p[1]; x.qy=p[2]; x.qz=p[3]; x.tx=p[4]; x.ty=p[5]; x.tz=p[6];
    return x;
}
__device__ __forceinline__ void pair_store_g(float* p, const Pose& e, const Pose& g) {
    *(float4*)(p)      = make_float4(e.qw, e.qx, e.qy, e.qz);
    *(float4*)(p + 4)  = make_float4(e.tx, e.ty, e.tz, 0.f);
    *(float4*)(p + 8)  = make_float4(g.qw, g.qx, g.qy, g.qz);
    *(float4*)(p + 12) = make_float4(g.tx, g.ty, g.tz, 0.f);
}
__device__ __forceinline__ void pair_load_g(const float* p, Pose& e, Pose& g) {
    float4 a = *(const float4*)(p),     b = *(const float4*)(p + 4);
    float4 c = *(const float4*)(p + 8), d = *(const float4*)(p + 12);
    e.qw=a.x; e.qx=a.y; e.qy=a.z; e.qz=a.w; e.tx=b.x; e.ty=b.y; e.tz=b.z;
    g.qw=c.x; g.qx=c.y; g.qy=c.z; g.qz=c.w; g.tx=d.x; g.ty=d.y; g.tz=d.z;
}

// Single fused kernel: EPT=4 (best-measured config) with a contention-free
// reduction tail (per-block partial stores; NO same-address atomicAdd storm).
__global__ void __launch_bounds__(NTHREADS) k_main(
    const float* __restrict__ yhat, const float* __restrict__ gpos,
    const float* __restrict__ gori, float* __restrict__ out) {
    __shared__ float sS[NTHREADS][SS_STRIDE];  // E prefixes @0,7,14; G @21,28,35
    __shared__ float sw[2][NWARPS][8];
    __shared__ float sexc[2][8];
    __shared__ float sred[6][NWARPS];
    __shared__ int   s_last;
    int tid = threadIdx.x, lane = tid & 31, wid = tid >> 5;
    int bid = blockIdx.x;
    int batch = bid >> 3, chunk = bid & (CHUNKS - 1);
    int s0 = chunk * CHUNK + tid * EPT;
    int idx0 = batch * NS + s0;

    // ---- inputs (all float4 aligned: idx0 % 4 == 0) ----
    const float4* y4 = (const float4*)(yhat + (size_t)idx0 * 6);
    float4 y0 = y4[0], y1 = y4[1], y2 = y4[2], y3 = y4[3], y4v = y4[4], y5 = y4[5];
    const float4* o4 = (const float4*)(gori + (size_t)idx0 * 3);
    float4 q0 = o4[0], q1 = o4[1], q2 = o4[2];
    const float4* p4 = (const float4*)(gpos + (size_t)idx0 * 3);
    float4 p0 = p4[0], p1 = p4[1], p2 = p4[2];

    float ea[4][3] = {{y0.x,y0.y,y0.z},{y1.z,y1.w,y2.x},{y3.x,y3.y,y3.z},{y4v.z,y4v.w,y5.x}};
    float et[4][3] = {{y0.w,y1.x,y1.y},{y2.y,y2.z,y2.w},{y3.w,y4v.x,y4v.y},{y5.y,y5.z,y5.w}};
    float ga[4][3] = {{q0.x,q0.y,q0.z},{q0.w,q1.x,q1.y},{q1.z,q1.w,q2.x},{q2.y,q2.z,q2.w}};
    float gt[4][3] = {{p0.x,p0.y,p0.z},{p0.w,p1.x,p1.y},{p1.z,p1.w,p2.x},{p2.y,p2.z,p2.w}};

    // ---- build 4 poses/stream, odom terms, serial prefixes ----
    float acc[6] = {0.f, 0.f, 0.f, 0.f, 0.f, 0.f};
    Pose IE, IG;
#pragma unroll
    for (int i = 0; i < EPT; i++) {
        Pose E, G;
        euler_to_quat(ea[i][0], ea[i][1], ea[i][2], E);
        E.tx = et[i][0]; E.ty = et[i][1]; E.tz = et[i][2];
        euler_to_quat(ga[i][0], ga[i][1], ga[i][2], G);
        G.tx = gt[i][0]; G.ty = gt[i][1]; G.tz = gt[i][2];
#pragma unroll
        for (int k = 0; k < 3; k++) {
            float d = (&E.tx)[k] - (&G.tx)[k];
            acc[0] = fmaf(d, d, acc[0]);
            acc[1] += fabsf(d);
        }
        // odom angle: raw quats are unit (|q| = 1 +- 4e-6) -> skip normalization
        float dq = E.qw*G.qw + E.qx*G.qx + E.qy*G.qy + E.qz*G.qz;
        acc[2] += acos_fast(clamp_c(fmaf(2.f * dq, dq, -1.f)));
        if (s0 == 0 && i == 0) { E = pidentity(); G = pidentity(); }
        if (i == 0) { IE = E; IG = G; }
        else        { IE = pcompose(IE, E); IG = pcompose(IG, G); }
        if (i < EPT - 1) {
            pstore_s(&sS[tid][i * 7], IE);
            pstore_s(&sS[tid][21 + i * 7], IG);
        }
    }
    Pose TAe = IE, TAg = IG;   // thread aggregates (survive warp scan)

    // ---- warp-level inclusive scan over thread aggregates ----
#pragma unroll
    for (int off = 1; off < 32; off <<= 1) {
        Pose le = pshfl_up(IE, off), lg = pshfl_up(IG, off);
        if (lane >= off) { IE = pcompose(le, IE); IG = pcompose(lg, IG); }
    }
    if (lane == 31) { pstore_s(sw[0][wid], IE); pstore_s(sw[1][wid], IG); }
    __syncthreads();

    // ---- cross-warp scan (warp 0, 4 entries -> 2 steps) ----
    if (wid == 0) {
        Pose te = (lane < NWARPS) ? pload_s(sw[0][lane]) : pidentity();
        Pose tg = (lane < NWARPS) ? pload_s(sw[1][lane]) : pidentity();
#pragma unroll
        for (int off = 1; off < NWARPS; off <<= 1) {
            Pose le = pshfl_up(te, off), lg = pshfl_up(tg, off);
            if (lane >= off && lane < NWARPS) { te = pcompose(le, te); tg = pcompose(lg, tg); }
        }
        if (lane < NWARPS) { pstore_s(sw[0][lane], te); pstore_s(sw[1][lane], tg); }
    }
    __syncthreads();

    // ---- thread 0: publish aggregate, lookback (depth <= 7), publish prefix ----
    if (tid == 0) {
        int gen = *(volatile int*)&g_gen;
        int fagg = 2 * gen, fpre = 2 * gen + 1;
        Pose aE = pload_s(sw[0][NWARPS - 1]);
        Pose aG = pload_s(sw[1][NWARPS - 1]);
        pnormq(aE); pnormq(aG);   // cap norm drift at chunk length
        if (chunk < CHUNKS - 1) {
            pair_store_g(g_agg[bid], aE, aG);
            __threadfence();
            atomicExch(&g_flag[bid], fagg);
        }
        Pose excE = pidentity(), excG = pidentity();
        if (chunk > 0) {
            Pose accE = pidentity(), accG = pidentity();
            bool have = false;
            int base = batch * CHUNKS;
            for (int i = bid - 1; i >= base; --i) {
                int f;
                volatile int* vf = g_flag;
                while ((f = vf[i]) < fagg) { __nanosleep(20); }
                __threadfence();
                Pose pE, pG;
                if (f == fpre) {
                    pair_load_g(g_pre[i], pE, pG);
                    excE = pcompose(pE, accE);
                    excG = pcompose(pG, accG);
                    have = true;
                    break;
                } else {
                    pair_load_g(g_agg[i], pE, pG);
                    accE = pcompose(pE, accE);
                    accG = pcompose(pG, accG);
                }
            }
            if (!have) { excE = accE; excG = accG; }
            pnormq(excE); pnormq(excG);
        }
        if (chunk < CHUNKS - 1) {
            Pose pE = pcompose(excE, aE), pG = pcompose(excG, aG);
            pnormq(pE); pnormq(pG);
            pair_store_g(g_pre[bid], pE, pG);
            __threadfence();
            atomicExch(&g_flag[bid], fpre);
        }
        pstore_s(sexc[0], excE);
        pstore_s(sexc[1], excG);
    }
    __syncthreads();

    // ---- apply prefixes, trajectory losses (4 elems) ----
    Pose baseE = pload_s(sexc[0]);
    Pose baseG = pload_s(sexc[1]);
    if (wid > 0) {
        baseE = pcompose(baseE, pload_s(sw[0][wid - 1]));
        baseG = pcompose(baseG, pload_s(sw[1][wid - 1]));
    }
    Pose LEe = pshfl_up(IE, 1), LEg = pshfl_up(IG, 1);
    Pose preE = (lane == 0) ? baseE : pcompose(baseE, LEe);
    Pose preG = (lane == 0) ? baseG : pcompose(baseG, LEg);

    // per-thread relative quat + norm product (amortized over 4 elements)
    Quat r0 = qconj_mul(preG, preE);
    float K0 = qn2p(preE) * qn2p(preG);

#pragma unroll
    for (int i = 0; i < EPT - 1; i++)
        traj_term(preE, preG, r0, K0,
                  pload_s(&sS[tid][i * 7]), pload_s(&sS[tid][21 + i * 7]), acc);
    traj_term(preE, preG, r0, K0, TAe, TAg, acc);   // i = 3: thread aggregate (regs)

    // ---- block reduction -> contention-free partial store ----
#pragma unroll
    for (int o = 16; o > 0; o >>= 1)
#pragma unroll
        for (int j = 0; j < 6; j++) acc[j] += __shfl_down_sync(FULLMASK, acc[j], o);
    if (lane == 0)
#pragma unroll
        for (int j = 0; j < 6; j++) sred[j][wid] = acc[j];
    __syncthreads();
    if (tid == 0) {
#pragma unroll
        for (int j = 0; j < 6; j++) {
            float s = sred[j][0];
#pragma unroll
            for (int i = 1; i < NWARPS; i++) s += sred[j][i];
            g_partial[j][bid] = s;      // plain store, unique address per block
        }
        __threadfence();
        int old = atomicAdd(&g_done, 1);   // single cheap atomic per block
        s_last = (old == NBLOCKS - 1) ? 1 : 0;
    }
    __syncthreads();

    // ---- last block: parallel final reduction over g_partial ----
    if (s_last) {
        __shared__ double stot[6];
        for (int j = wid; j < 6; j += NWARPS) {
            double s = 0.0;
            for (int i = lane; i < NBLOCKS; i += 32) s += (double)g_partial[j][i];
#pragma unroll
            for (int o = 16; o > 0; o >>= 1) s += __shfl_down_sync(FULLMASK, s, o);
            if (lane == 0) stot[j] = s;
        }
        __syncthreads();
        if (tid == 0) {
            const double n3 = (double)NELEM * 3.0, n1 = (double)NELEM;
            double odom = stot[2] / n1 + (stot[0] / n3 + stot[1] / n3);
            double traj = stot[5] / n1 + (stot[3] / n3 + stot[4] / n3);
            out[0] = (float)(0.5 * odom + 0.5 * traj);
            g_done = 0;
            __threadfence();
            g_gen = *(volatile int*)&g_gen + 1;
        }
    }
}

extern "C" void kernel_launch(void* const* d_in, const int* in_sizes, int n_in,
                              void* d_out, int out_size) {
    const float* yhat = (const float*)d_in[0];
    const float* gpos = (const float*)d_in[1];
    const float* gori = (const float*)d_in[2];
    k_main<<<NBLOCKS, NTHREADS>>>(yhat, gpos, gori, (float*)d_out);
}